// round 7
// baseline (speedup 1.0000x reference)
#include <cuda_runtime.h>
#include <cuda_bf16.h>

// LRN spatial 5x5: out = x / (2 + 1e-4 * boxsum5x5(x^2))^0.75
// x: (16, 96, 224, 224) fp32, zero padding.
//
// R7: R5 compute core + persistent strip pipeline with register prefetch.
//   Block = half-plane (112 rows) = 4 strips of 28 rows, 224 threads.
//   Per strip: STS prefetched regs -> barrier -> issue next strip's 8
//   LDG.128 (consumed a full compute-phase later -> DRAM latency hidden,
//   loads overlap compute) -> compute strip:
//     3 aligned LDS.128 -> horizontal 5-tap ssq sliding sum (4 cols/thread),
//     vertical 5-tap register ring, __powf(d,-0.75), STG.128.
//   cp.async reverted: LDGSTS rt=8cyc/op only wins at N>=32 (we have N=8).

#define LRN_W   224
#define LRN_H   224
#define LRN_TH  28                   // rows per strip
#define LRN_NS  4                    // strips per block (112 rows)
#define LRN_TR  (LRN_TH + 4)         // 32 tile rows
#define LRN_XSW 232                  // 4 pad + 224 + 4 pad
#define LRN_CG  56                   // col-groups per row
#define LRN_LPT ((LRN_TR * LRN_CG) / 224)   // 8 float4 loads per thread
#define LRN_R   (LRN_TH / 4)         // 7 rows per row-group

// Horizontal 5-tap sum-of-squares for 4 columns at shared index g4..g4+3.
__device__ __forceinline__ float4 hsum_row(const float* __restrict__ rowp,
                                           int g4, float4* __restrict__ bx) {
    float4 a = *reinterpret_cast<const float4*>(rowp + g4);
    float4 b = *reinterpret_cast<const float4*>(rowp + g4 + 4);
    float4 c = *reinterpret_cast<const float4*>(rowp + g4 + 8);
    *bx = b;
    float q0 = a.z * a.z, q1 = a.w * a.w;
    float q2 = b.x * b.x, q3 = b.y * b.y;
    float q4 = b.z * b.z, q5 = b.w * b.w;
    float q6 = c.x * c.x, q7 = c.y * c.y;
    float4 h;
    h.x = q0 + q1 + q2 + q3 + q4;
    h.y = h.x - q0 + q5;
    h.z = h.y - q1 + q6;
    h.w = h.z - q2 + q7;
    return h;
}

__global__ __launch_bounds__(224, 3)
void lrn_kernel(const float* __restrict__ x, float* __restrict__ out) {
    __shared__ float xs[LRN_TR][LRN_XSW];   // global col c -> idx c+4

    const int plane = blockIdx.x;                  // n*96 + c
    const int rbase = blockIdx.y * (LRN_TH * LRN_NS);   // 0 or 112
    const int tid   = threadIdx.x;
    const float* __restrict__ px   = x   + (size_t)plane * (LRN_H * LRN_W);
    float*       __restrict__ pout = out + (size_t)plane * (LRN_H * LRN_W);

    // Per-thread tile coordinates for the 8 prefetch groups.
    // k-th group: gg = k*224+tid, row = gg/56, c4 = (gg%56)*4.

    // Column pads are constant zero for all strips; write once.
    if (tid < LRN_TR * 4) {
        int row = tid >> 2;
        int j   = tid & 3;
        int idx = (j < 2) ? (2 + j) : (226 + j);   // 2,3,228,229
        xs[row][idx] = 0.f;
    }

    // Prefetch strip 0 (tile rows rbase-2 .. rbase+29) into registers.
    float4 pf[LRN_LPT];
    #pragma unroll
    for (int k = 0; k < LRN_LPT; ++k) {
        int gg   = k * 224 + tid;
        int row  = gg / LRN_CG;
        int c4   = (gg % LRN_CG) * 4;
        int grow = rbase - 2 + row;
        float4 v = make_float4(0.f, 0.f, 0.f, 0.f);
        if (grow >= 0 && grow < LRN_H)
            v = *reinterpret_cast<const float4*>(px + (size_t)grow * LRN_W + c4);
        pf[k] = v;
    }

    // Stream-phase thread mapping.
    const int g4  = (tid % LRN_CG) * 4;      // shared col-group base index
    const int srg = tid / LRN_CG;            // row-group 0..3
    const int ti0 = srg * LRN_R + 2;         // tile row of first output row

    for (int s = 0; s < LRN_NS; ++s) {
        const int r0 = rbase + s * LRN_TH;

        if (s) __syncthreads();              // prev compute done reading xs

        // Drain prefetch regs into shared.
        #pragma unroll
        for (int k = 0; k < LRN_LPT; ++k) {
            int gg  = k * 224 + tid;
            int row = gg / LRN_CG;
            int c4  = (gg % LRN_CG) * 4;
            *reinterpret_cast<float4*>(&xs[row][4 + c4]) = pf[k];
        }
        __syncthreads();                     // tile ready

        // Issue next strip's loads now; consumed at next STS (fully hidden).
        if (s + 1 < LRN_NS) {
            const int rn = r0 + LRN_TH;
            #pragma unroll
            for (int k = 0; k < LRN_LPT; ++k) {
                int gg   = k * 224 + tid;
                int row  = gg / LRN_CG;
                int c4   = (gg % LRN_CG) * 4;
                int grow = rn - 2 + row;
                float4 v = make_float4(0.f, 0.f, 0.f, 0.f);
                if (grow >= 0 && grow < LRN_H)
                    v = *reinterpret_cast<const float4*>(px + (size_t)grow * LRN_W + c4);
                pf[k] = v;
            }
        }

        // ---- Compute strip s: 7 rows per row-group ----
        const int sr0 = r0 + srg * LRN_R;    // global first output row

        float4 bx;
        float4 hist[4];
        float4 xr[2];
        hist[0] = hsum_row(&xs[ti0 - 2][0], g4, &bx);
        hist[1] = hsum_row(&xs[ti0 - 1][0], g4, &bx);
        hist[2] = hsum_row(&xs[ti0    ][0], g4, &bx);  xr[0] = bx;
        hist[3] = hsum_row(&xs[ti0 + 1][0], g4, &bx);  xr[1] = bx;

        float4 vs;
        vs.x = hist[0].x + hist[1].x + hist[2].x + hist[3].x;
        vs.y = hist[0].y + hist[1].y + hist[2].y + hist[3].y;
        vs.z = hist[0].z + hist[1].z + hist[2].z + hist[3].z;
        vs.w = hist[0].w + hist[1].w + hist[2].w + hist[3].w;

        float* po = pout + (size_t)sr0 * LRN_W + g4;

        #pragma unroll
        for (int i = 0; i < LRN_R; ++i) {
            float4 hnew = hsum_row(&xs[ti0 + 2 + i][0], g4, &bx);

            float4 vf;                        // vertical 5-tap ssq @ row sr0+i
            vf.x = vs.x + hnew.x;
            vf.y = vs.y + hnew.y;
            vf.z = vs.z + hnew.z;
            vf.w = vs.w + hnew.w;

            float4 xa = xr[i & 1];            // raw x @ row sr0+i
            float4 val;
            val.x = xa.x * __powf(fmaf(1e-4f, vf.x, 2.0f), -0.75f);
            val.y = xa.y * __powf(fmaf(1e-4f, vf.y, 2.0f), -0.75f);
            val.z = xa.z * __powf(fmaf(1e-4f, vf.z, 2.0f), -0.75f);
            val.w = xa.w * __powf(fmaf(1e-4f, vf.w, 2.0f), -0.75f);

            *reinterpret_cast<float4*>(po) = val;
            po += LRN_W;

            float4 hold = hist[i & 3];        // h @ row sr0+i-2
            vs.x = vf.x - hold.x;
            vs.y = vf.y - hold.y;
            vs.z = vf.z - hold.z;
            vs.w = vf.w - hold.w;
            hist[i & 3] = hnew;
            xr[i & 1] = bx;
        }
    }
}

extern "C" void kernel_launch(void* const* d_in, const int* in_sizes, int n_in,
                              void* d_out, int out_size) {
    const float* x = (const float*)d_in[0];
    float* out = (float*)d_out;
    (void)in_sizes; (void)n_in; (void)out_size;
    dim3 grid(16 * 96, LRN_H / (LRN_TH * LRN_NS));   // 1536 planes x 2 halves
    lrn_kernel<<<grid, 224>>>(x, out);
}

// round 8
// speedup vs baseline: 1.2626x; 1.2626x over previous
#include <cuda_runtime.h>
#include <cuda_bf16.h>

// LRN spatial 5x5: out = x / (2 + 1e-4 * boxsum5x5(x^2))^0.75
// x: (16, 96, 224, 224) fp32, zero padding.
//
// R8 = R5 (best measured core) + register ceiling for 5 blocks/SM.
//   Block = 32 output rows x 224 cols (+2-row halo tile in smem), 224 thr.
//   Phase A: coalesced float4 LDG->STS tile load (ptxas batches under the
//            58-reg cap; block-level MLP stays high).
//   Stream:  thread owns 4 cols x 8 rows. Per row: 3 aligned LDS.128 ->
//            horizontal 5-tap ssq register sliding sum; vertical 5-tap via
//            register ring hist[4]; d^-0.75 = __powf (LG2+FMUL+EX2);
//            STG.128 output, all lanes useful.
//   Pipeline/cp.async variants measured slower (R6: 121us, R7: 129us).

#define LRN_W   224
#define LRN_H   224
#define LRN_R   8                    // rows per row-group
#define LRN_RG  4                    // row-groups per block
#define LRN_TH  (LRN_R * LRN_RG)     // 32 output rows per block
#define LRN_TR  (LRN_TH + 4)         // 36 tile rows
#define LRN_XSW 232                  // 4 pad + 224 + 4 pad
#define LRN_CG  56                   // col-groups per row

// Horizontal 5-tap sum-of-squares for 4 columns starting at shared idx g4+4.
__device__ __forceinline__ float4 hsum_row(const float* __restrict__ rowp,
                                           int g4, float4* __restrict__ bx) {
    float4 a = *reinterpret_cast<const float4*>(rowp + g4);
    float4 b = *reinterpret_cast<const float4*>(rowp + g4 + 4);
    float4 c = *reinterpret_cast<const float4*>(rowp + g4 + 8);
    *bx = b;
    float q0 = a.z * a.z, q1 = a.w * a.w;
    float q2 = b.x * b.x, q3 = b.y * b.y;
    float q4 = b.z * b.z, q5 = b.w * b.w;
    float q6 = c.x * c.x, q7 = c.y * c.y;
    float4 h;
    h.x = q0 + q1 + q2 + q3 + q4;
    h.y = h.x - q0 + q5;
    h.z = h.y - q1 + q6;
    h.w = h.z - q2 + q7;
    return h;
}

__global__ __launch_bounds__(224, 5)
void lrn_kernel(const float* __restrict__ x, float* __restrict__ out) {
    __shared__ float xs[LRN_TR][LRN_XSW];   // global col c -> idx c+4

    const int plane = blockIdx.x;                 // n*96 + c
    const int r0    = blockIdx.y * LRN_TH;        // 0,32,...,192
    const int tid   = threadIdx.x;
    const float* __restrict__ px   = x   + (size_t)plane * (LRN_H * LRN_W);
    float*       __restrict__ pout = out + (size_t)plane * (LRN_H * LRN_W);

    // ---- Phase A: coalesced float4 tile load (rows r0-2 .. r0+33) ----
    #pragma unroll
    for (int k = 0; k < (LRN_TR * LRN_CG) / 224; ++k) {   // 9 per thread
        int gg   = k * 224 + tid;
        int row  = gg / LRN_CG;
        int c4   = (gg % LRN_CG) * 4;
        int grow = r0 - 2 + row;
        float4 v = make_float4(0.f, 0.f, 0.f, 0.f);
        if (grow >= 0 && grow < LRN_H)
            v = *reinterpret_cast<const float4*>(px + (size_t)grow * LRN_W + c4);
        *reinterpret_cast<float4*>(&xs[row][4 + c4]) = v;
    }
    // zero column pads (idx 2,3 = cols -2,-1; idx 228,229 = cols 224,225)
    if (tid < LRN_TR * 4) {
        int row = tid >> 2;
        int j   = tid & 3;
        int idx = (j < 2) ? (2 + j) : (226 + j);
        xs[row][idx] = 0.f;
    }
    __syncthreads();

    // ---- Stream phase: 56 col-groups x 4 row-groups ----
    const int g4  = (tid % LRN_CG) * 4;     // shared base index of col-group
    const int s   = tid / LRN_CG;           // row-group 0..3
    const int ti0 = s * LRN_R + 2;          // tile row of first output row
    const int sr0 = r0 + s * LRN_R;         // global first output row

    float4 bx;
    float4 hist[4];
    float4 xr[2];
    hist[0] = hsum_row(&xs[ti0 - 2][0], g4, &bx);
    hist[1] = hsum_row(&xs[ti0 - 1][0], g4, &bx);
    hist[2] = hsum_row(&xs[ti0    ][0], g4, &bx);  xr[0] = bx;
    hist[3] = hsum_row(&xs[ti0 + 1][0], g4, &bx);  xr[1] = bx;

    float4 vs;
    vs.x = hist[0].x + hist[1].x + hist[2].x + hist[3].x;
    vs.y = hist[0].y + hist[1].y + hist[2].y + hist[3].y;
    vs.z = hist[0].z + hist[1].z + hist[2].z + hist[3].z;
    vs.w = hist[0].w + hist[1].w + hist[2].w + hist[3].w;

    float* po = pout + (size_t)sr0 * LRN_W + g4;

    #pragma unroll
    for (int i = 0; i < LRN_R; ++i) {
        float4 hnew = hsum_row(&xs[ti0 + 2 + i][0], g4, &bx);

        float4 vf;                           // vertical 5-tap ssq @ row sr0+i
        vf.x = vs.x + hnew.x;
        vf.y = vs.y + hnew.y;
        vf.z = vs.z + hnew.z;
        vf.w = vs.w + hnew.w;

        float4 xa = xr[i & 1];               // raw x @ row sr0+i
        float4 val;
        val.x = xa.x * __powf(fmaf(1e-4f, vf.x, 2.0f), -0.75f);
        val.y = xa.y * __powf(fmaf(1e-4f, vf.y, 2.0f), -0.75f);
        val.z = xa.z * __powf(fmaf(1e-4f, vf.z, 2.0f), -0.75f);
        val.w = xa.w * __powf(fmaf(1e-4f, vf.w, 2.0f), -0.75f);

        *reinterpret_cast<float4*>(po) = val;
        po += LRN_W;

        float4 hold = hist[i & 3];           // h @ row sr0+i-2
        vs.x = vf.x - hold.x;
        vs.y = vf.y - hold.y;
        vs.z = vf.z - hold.z;
        vs.w = vf.w - hold.w;
        hist[i & 3] = hnew;
        xr[i & 1] = bx;
    }
}

extern "C" void kernel_launch(void* const* d_in, const int* in_sizes, int n_in,
                              void* d_out, int out_size) {
    const float* x = (const float*)d_in[0];
    float* out = (float*)d_out;
    (void)in_sizes; (void)n_in; (void)out_size;
    dim3 grid(16 * 96, LRN_H / LRN_TH);    // 1536 planes x 7 row-strips
    lrn_kernel<<<grid, 224>>>(x, out);
}